// round 1
// baseline (speedup 1.0000x reference)
#include <cuda_runtime.h>

// Anisotropic RBF kernel matrix on GB300:
//   out[n][m] = exp(2 * x[n] . (gamma*y[m]) - sqx[n] - sqy[m])
// N = M = 8192, D = 64, fp32 throughout (precision: exponent needs ~1e-5 rel acc).

#define NROWS 8192
#define MROWS 8192
#define DDIM  64

// Scratch for precomputed gamma-weighted squared norms (no allocs allowed).
__device__ float g_sqx[NROWS];
__device__ float g_sqy[MROWS];

// ---- packed fp32x2 helpers (sm_100+ PTX; FFMA2 in SASS, 2x fp32 rate) ----
__device__ __forceinline__ unsigned long long ffma2(unsigned long long a,
                                                    unsigned long long b,
                                                    unsigned long long c) {
    unsigned long long d;
    asm("fma.rn.f32x2 %0, %1, %2, %3;" : "=l"(d) : "l"(a), "l"(b), "l"(c));
    return d;
}
__device__ __forceinline__ unsigned long long bcast2(float a) {
    unsigned long long v;
    unsigned u = __float_as_uint(a);
    asm("mov.b64 %0, {%1, %2};" : "=l"(v) : "r"(u), "r"(u));
    return v;
}
__device__ __forceinline__ float2 unpack2(unsigned long long v) {
    unsigned lo, hi;
    asm("mov.b64 {%0, %1}, %2;" : "=r"(lo), "=r"(hi) : "l"(v));
    return make_float2(__uint_as_float(lo), __uint_as_float(hi));
}

// ---- precompute sqx[n] = sum_d gamma_d x[n][d]^2 (one warp per row) ----
__global__ void precompute_kernel(const float* __restrict__ x,
                                  const float* __restrict__ y,
                                  const float* __restrict__ gamma) {
    int w = (blockIdx.x * blockDim.x + threadIdx.x) >> 5;
    int lane = threadIdx.x & 31;
    const float* src;
    float* dst;
    int row;
    if (w < NROWS) { src = x; dst = g_sqx; row = w; }
    else           { src = y; dst = g_sqy; row = w - NROWS; }
    float g0 = gamma[lane], g1 = gamma[lane + 32];
    float v0 = src[(size_t)row * DDIM + lane];
    float v1 = src[(size_t)row * DDIM + lane + 32];
    float s = g0 * v0 * v0 + g1 * v1 * v1;
    #pragma unroll
    for (int o = 16; o > 0; o >>= 1) s += __shfl_xor_sync(0xffffffffu, s, o);
    if (lane == 0) dst[row] = s;
}

// ---- main fused kernel: 128x128 tile per CTA, 8x8 per thread, K=64 resident ----
// smem tiles are k-major [64][128] floats with a float4-level XOR swizzle:
//   phys_float4(k, i4) = k*32 + (i4 ^ ((k>>2) & 7))
// which makes the global->smem transpose stores bank-spread (4-phase STS.128,
// optimal) while mainloop LDS.128 reads stay conflict-light.
__global__ __launch_bounds__(256, 2) void rbf_main_kernel(
    const float* __restrict__ x, const float* __restrict__ y,
    const float* __restrict__ gamma, float* __restrict__ out)
{
    extern __shared__ float smem[];
    float4* xs4 = reinterpret_cast<float4*>(smem);          // 64*32 float4 = 32KB
    float4* ys4 = reinterpret_cast<float4*>(smem + 8192);   // 32KB

    const int tid = threadIdx.x;
    const int tx = tid & 15;     // 16 col-threads
    const int ty = tid >> 4;     // 16 row-threads
    const int rowBase = blockIdx.y * 128;
    const int colBase = blockIdx.x * 128;

    const float4* gx4 = reinterpret_cast<const float4*>(x + (size_t)rowBase * DDIM);
    const float4* gy4 = reinterpret_cast<const float4*>(y + (size_t)colBase * DDIM);
    const float4* gg4 = reinterpret_cast<const float4*>(gamma);

    // -- load tiles with in-register 4x4 transpose into swizzled k-major smem --
    #pragma unroll
    for (int it = 0; it < 2; ++it) {
        int idx = tid + it * 256;
        int c4 = idx & 15;   // d-chunk (4 dims)
        int r4 = idx >> 4;   // row-chunk of 4 (0..31)
        float vx[4][4], vy[4][4];
        #pragma unroll
        for (int s = 0; s < 4; ++s) {
            float4 t = gx4[((size_t)(r4 * 4 + s)) * 16 + c4];
            vx[s][0] = t.x; vx[s][1] = t.y; vx[s][2] = t.z; vx[s][3] = t.w;
            float4 u = gy4[((size_t)(r4 * 4 + s)) * 16 + c4];
            vy[s][0] = u.x; vy[s][1] = u.y; vy[s][2] = u.z; vy[s][3] = u.w;
        }
        float4 g = gg4[c4];
        // fold the factor 2 of the cross term into the y tile
        float gs[4] = {2.f * g.x, 2.f * g.y, 2.f * g.z, 2.f * g.w};
        #pragma unroll
        for (int j = 0; j < 4; ++j) {
            int k = c4 * 4 + j;
            int phys = k * 32 + (r4 ^ (c4 & 7));
            xs4[phys] = make_float4(vx[0][j], vx[1][j], vx[2][j], vx[3][j]);
            ys4[phys] = make_float4(vy[0][j] * gs[j], vy[1][j] * gs[j],
                                    vy[2][j] * gs[j], vy[3][j] * gs[j]);
        }
    }
    __syncthreads();

    // -- mainloop: 8x8 outer product per k, packed f32x2 (2 cols per FFMA2) --
    unsigned long long acc[8][4];
    #pragma unroll
    for (int r = 0; r < 8; ++r)
        #pragma unroll
        for (int p = 0; p < 4; ++p) acc[r][p] = 0ull;

    const ulonglong2* ysu = reinterpret_cast<const ulonglong2*>(smem + 8192);
    const int i4a = 2 * ty;
    const int j4b = 2 * tx;

    #pragma unroll 16
    for (int k = 0; k < 64; ++k) {
        int s = (k >> 2) & 7;
        float4 a0 = xs4[k * 32 + (i4a ^ s)];
        float4 a1 = xs4[k * 32 + ((i4a + 1) ^ s)];
        ulonglong2 b0 = ysu[k * 32 + (j4b ^ s)];
        ulonglong2 b1 = ysu[k * 32 + ((j4b + 1) ^ s)];
        unsigned long long bb[4] = {b0.x, b0.y, b1.x, b1.y};
        float av[8] = {a0.x, a0.y, a0.z, a0.w, a1.x, a1.y, a1.z, a1.w};
        #pragma unroll
        for (int r = 0; r < 8; ++r) {
            unsigned long long aa = bcast2(av[r]);
            #pragma unroll
            for (int p = 0; p < 4; ++p)
                acc[r][p] = ffma2(aa, bb[p], acc[r][p]);
        }
    }

    // -- epilogue: exponent + exp + coalesced float4 stores --
    float sy[8];
    #pragma unroll
    for (int c = 0; c < 8; ++c) sy[c] = g_sqy[colBase + tx * 8 + c];

    #pragma unroll
    for (int r = 0; r < 8; ++r) {
        int row = rowBase + ty * 8 + r;
        float sx = g_sqx[row];
        float o[8];
        #pragma unroll
        for (int p = 0; p < 4; ++p) {
            float2 u = unpack2(acc[r][p]);
            o[2 * p]     = u.x;
            o[2 * p + 1] = u.y;
        }
        float4 w0, w1;
        w0.x = __expf(o[0] - sx - sy[0]);
        w0.y = __expf(o[1] - sx - sy[1]);
        w0.z = __expf(o[2] - sx - sy[2]);
        w0.w = __expf(o[3] - sx - sy[3]);
        w1.x = __expf(o[4] - sx - sy[4]);
        w1.y = __expf(o[5] - sx - sy[5]);
        w1.z = __expf(o[6] - sx - sy[6]);
        w1.w = __expf(o[7] - sx - sy[7]);
        float4* op = reinterpret_cast<float4*>(out + (size_t)row * MROWS + colBase + tx * 8);
        op[0] = w0;
        op[1] = w1;
    }
}

extern "C" void kernel_launch(void* const* d_in, const int* in_sizes, int n_in,
                              void* d_out, int out_size) {
    const float* x     = (const float*)d_in[0];
    const float* y     = (const float*)d_in[1];
    const float* gamma = (const float*)d_in[2];
    float* out = (float*)d_out;
    (void)in_sizes; (void)n_in; (void)out_size;

    // 64KB dynamic smem (> 48KB static limit); idempotent, graph-safe.
    cudaFuncSetAttribute(rbf_main_kernel,
                         cudaFuncAttributeMaxDynamicSharedMemorySize, 65536);

    // 16384 rows total (x then y), one warp each: 524288 threads.
    precompute_kernel<<<2048, 256>>>(x, y, gamma);
    rbf_main_kernel<<<dim3(64, 64), 256, 65536>>>(x, y, gamma, out);
}

// round 3
// speedup vs baseline: 1.1280x; 1.1280x over previous
#include <cuda_runtime.h>

// Anisotropic RBF kernel matrix on GB300:
//   out[n][m] = exp(2 * x[n] . (gamma*y[m]) - sqx[n] - sqy[m])
// N = M = 8192, D = 64, fp32 throughout.
// R1 (resubmitted after infra failure): rebalanced smem wavefronts —
// row-pair-packed accumulators, split column quads so every b-load LDS.128
// hits contiguous fully-used 128B lines.

#define NROWS 8192
#define MROWS 8192
#define DDIM  64

__device__ float g_sqx[NROWS];
__device__ float g_sqy[MROWS];

// ---- packed fp32x2 helpers (FFMA2 in SASS, 2x fp32 rate) ----
__device__ __forceinline__ unsigned long long ffma2(unsigned long long a,
                                                    unsigned long long b,
                                                    unsigned long long c) {
    unsigned long long d;
    asm("fma.rn.f32x2 %0, %1, %2, %3;" : "=l"(d) : "l"(a), "l"(b), "l"(c));
    return d;
}
__device__ __forceinline__ unsigned long long bcast2(float a) {
    unsigned long long v;
    unsigned u = __float_as_uint(a);
    asm("mov.b64 %0, {%1, %2};" : "=l"(v) : "r"(u), "r"(u));
    return v;
}
__device__ __forceinline__ float2 unpack2(unsigned long long v) {
    unsigned lo, hi;
    asm("mov.b64 {%0, %1}, %2;" : "=r"(lo), "=r"(hi) : "l"(v));
    return make_float2(__uint_as_float(lo), __uint_as_float(hi));
}

// ---- precompute gamma-weighted squared norms (one warp per row) ----
__global__ void precompute_kernel(const float* __restrict__ x,
                                  const float* __restrict__ y,
                                  const float* __restrict__ gamma) {
    int w = (blockIdx.x * blockDim.x + threadIdx.x) >> 5;
    int lane = threadIdx.x & 31;
    const float* src;
    float* dst;
    int row;
    if (w < NROWS) { src = x; dst = g_sqx; row = w; }
    else           { src = y; dst = g_sqy; row = w - NROWS; }
    float g0 = gamma[lane], g1 = gamma[lane + 32];
    float v0 = src[(size_t)row * DDIM + lane];
    float v1 = src[(size_t)row * DDIM + lane + 32];
    float s = g0 * v0 * v0 + g1 * v1 * v1;
    #pragma unroll
    for (int o = 16; o > 0; o >>= 1) s += __shfl_xor_sync(0xffffffffu, s, o);
    if (lane == 0) dst[row] = s;
}

// ---- main fused kernel: 128x128 tile / CTA, 8 rows x (4+4) cols / thread ----
// smem tiles: k-major [64][32] float4 slots with XOR swizzle
//   phys(k, slot) = k*32 + (slot ^ ((k>>2) & 7))
__global__ __launch_bounds__(256, 2) void rbf_main_kernel(
    const float* __restrict__ x, const float* __restrict__ y,
    const float* __restrict__ gamma, float* __restrict__ out)
{
    extern __shared__ float smem[];
    float4* xs4 = reinterpret_cast<float4*>(smem);          // 32KB
    float4* ys4 = reinterpret_cast<float4*>(smem + 8192);   // 32KB

    const int tid = threadIdx.x;
    const int tx = tid & 15;     // 16 col-threads: cols {4tx..+3} and {64+4tx..+3}
    const int ty = tid >> 4;     // 16 row-threads: rows 8ty..8ty+7
    const int rowBase = blockIdx.y * 128;
    const int colBase = blockIdx.x * 128;

    const float4* gx4 = reinterpret_cast<const float4*>(x + (size_t)rowBase * DDIM);
    const float4* gy4 = reinterpret_cast<const float4*>(y + (size_t)colBase * DDIM);
    const float4* gg4 = reinterpret_cast<const float4*>(gamma);

    // -- load tiles: in-register 4x4 transpose into swizzled k-major smem --
    #pragma unroll
    for (int it = 0; it < 2; ++it) {
        int idx = tid + it * 256;
        int c4 = idx & 15;   // d-chunk of 4
        int r4 = idx >> 4;   // row-chunk of 4 (0..31)
        float vx[4][4], vy[4][4];
        #pragma unroll
        for (int s = 0; s < 4; ++s) {
            float4 t = gx4[((size_t)(r4 * 4 + s)) * 16 + c4];
            vx[s][0] = t.x; vx[s][1] = t.y; vx[s][2] = t.z; vx[s][3] = t.w;
            float4 u = gy4[((size_t)(r4 * 4 + s)) * 16 + c4];
            vy[s][0] = u.x; vy[s][1] = u.y; vy[s][2] = u.z; vy[s][3] = u.w;
        }
        float4 g = gg4[c4];
        float gs[4] = {2.f * g.x, 2.f * g.y, 2.f * g.z, 2.f * g.w};  // fold 2x
        #pragma unroll
        for (int j = 0; j < 4; ++j) {
            int k = c4 * 4 + j;
            int phys = k * 32 + (r4 ^ (c4 & 7));
            xs4[phys] = make_float4(vx[0][j], vx[1][j], vx[2][j], vx[3][j]);
            ys4[phys] = make_float4(vy[0][j] * gs[j], vy[1][j] * gs[j],
                                    vy[2][j] * gs[j], vy[3][j] * gs[j]);
        }
    }
    __syncthreads();

    // -- mainloop: acc[rp][c] = packed rows (8ty+2rp, 8ty+2rp+1), col group c --
    unsigned long long acc[4][8];
    #pragma unroll
    for (int rp = 0; rp < 4; ++rp)
        #pragma unroll
        for (int c = 0; c < 8; ++c) acc[rp][c] = 0ull;

    const ulonglong2* xsu = reinterpret_cast<const ulonglong2*>(smem);

    #pragma unroll
    for (int k4 = 0; k4 < 16; ++k4) {
        const int s = k4 & 7;
        const int slotA0 = (2 * ty) ^ s;       // rows 8ty..8ty+3 (broadcast, 1 wf)
        const int slotA1 = (2 * ty + 1) ^ s;   // rows 8ty+4..8ty+7
        const int slotB0 = tx ^ s;             // cols 4tx..4tx+3   (contig, 2 wf)
        const int slotB1 = (tx + 16) ^ s;      // cols 64+4tx..+3   (contig, 2 wf)
        #pragma unroll
        for (int kk = 0; kk < 4; ++kk) {
            const int kb = (k4 * 4 + kk) * 32;
            ulonglong2 aA = xsu[kb + slotA0];
            ulonglong2 aB = xsu[kb + slotA1];
            float4 b0 = ys4[kb + slotB0];
            float4 b1 = ys4[kb + slotB1];
            unsigned long long ap[4] = {aA.x, aA.y, aB.x, aB.y};
            float bv[8] = {b0.x, b0.y, b0.z, b0.w, b1.x, b1.y, b1.z, b1.w};
            #pragma unroll
            for (int c = 0; c < 8; ++c) {
                unsigned long long bb = bcast2(bv[c]);
                #pragma unroll
                for (int rp = 0; rp < 4; ++rp)
                    acc[rp][c] = ffma2(ap[rp], bb, acc[rp][c]);
            }
        }
    }

    // -- epilogue: exponent + exp + two coalesced float4 stores per row --
    float syA[4], syB[4];
    #pragma unroll
    for (int j = 0; j < 4; ++j) {
        syA[j] = g_sqy[colBase + 4 * tx + j];
        syB[j] = g_sqy[colBase + 64 + 4 * tx + j];
    }

    #pragma unroll
    for (int rp = 0; rp < 4; ++rp) {
        float v0[8], v1[8];  // the two rows packed in this acc pair
        #pragma unroll
        for (int c = 0; c < 8; ++c) {
            float2 u = unpack2(acc[rp][c]);
            v0[c] = u.x;
            v1[c] = u.y;
        }
        #pragma unroll
        for (int h = 0; h < 2; ++h) {
            const float* v = h ? v1 : v0;
            int row = rowBase + 8 * ty + 2 * rp + h;
            float sx = g_sqx[row];
            float4 wA, wB;
            wA.x = __expf(v[0] - sx - syA[0]);
            wA.y = __expf(v[1] - sx - syA[1]);
            wA.z = __expf(v[2] - sx - syA[2]);
            wA.w = __expf(v[3] - sx - syA[3]);
            wB.x = __expf(v[4] - sx - syB[0]);
            wB.y = __expf(v[5] - sx - syB[1]);
            wB.z = __expf(v[6] - sx - syB[2]);
            wB.w = __expf(v[7] - sx - syB[3]);
            float* op = out + (size_t)row * MROWS + colBase;
            *reinterpret_cast<float4*>(op + 4 * tx) = wA;
            *reinterpret_cast<float4*>(op + 64 + 4 * tx) = wB;
        }
    }
}

extern "C" void kernel_launch(void* const* d_in, const int* in_sizes, int n_in,
                              void* d_out, int out_size) {
    const float* x     = (const float*)d_in[0];
    const float* y     = (const float*)d_in[1];
    const float* gamma = (const float*)d_in[2];
    float* out = (float*)d_out;
    (void)in_sizes; (void)n_in; (void)out_size;

    cudaFuncSetAttribute(rbf_main_kernel,
                         cudaFuncAttributeMaxDynamicSharedMemorySize, 65536);

    precompute_kernel<<<2048, 256>>>(x, y, gamma);
    rbf_main_kernel<<<dim3(64, 64), 256, 65536>>>(x, y, gamma, out);
}